// round 14
// baseline (speedup 1.0000x reference)
#include <cuda_runtime.h>
#include <cuda_fp16.h>
#include <cstdint>
#include <math.h>
#include <float.h>

// ---------------------------------------------------------------------------
// MultiBoxLoss (SSD) fused loss.  B=32, P=8732, C=81.
//   out[0] = loss_c / N, out[1] = loss_l / N
// Fully barrier-free warps: each warp stages its own 32-prior fp16 slice
// (__syncwarp only), computes per-prior nll from aligned half2 windows,
// shfl-reduces, and flushes with lane-0 atomics + a per-warp done ticket.
// ZERO __syncthreads in the kernel. The grid-last warp runs a warp-only
// finalizer. nll = lse - tgt_logit is both the CE term and the hard-negative
// rank key. Common case (num_neg >= #negatives): loss_c = sum of ALL nll.
// Rare case: exact top-k via radix select (tie-order invariant for a sum).
// ---------------------------------------------------------------------------

#define BATCH    32
#define PRIORS   8732
#define CLASSES  81
#define TPB      96                                // 3 autonomous warps
#define NWARP    3
#define WROWS    32                                // priors per warp slice
#define WHALF    (WROWS * CLASSES)                 // 2592 halves (5184 B)
#define SL_PER_B ((PRIORS + WROWS - 1) / WROWS)    // 273
#define SL_TOTAL (SL_PER_B * BATCH)                // 8736
#define GRID_MAIN (SL_TOTAL / NWARP)               // 2912
#define FULLMASK 0xFFFFFFFFu

// Device-global scratch; statically zero-init. The finalizer warp resets
// everything at the end of each call -> graph replays are deterministic.
__device__ double   g_sum_all[BATCH];
__device__ double   g_sum_pos[BATCH];
__device__ double   g_sum_loc[BATCH];
__device__ int      g_num_pos[BATCH];
__device__ unsigned g_done   = 0;
__device__ float    g_vrank[BATCH * PRIORS];

__global__ void __launch_bounds__(TPB, 14)
k_main(const float* __restrict__ conf,
       const float4* __restrict__ loc,
       const void*  __restrict__ ct,
       const float4* __restrict__ loct,
       float* __restrict__ out, int out_size) {
    __shared__ __align__(16) __half s_tile[NWARP][WHALF];   // 3 x 5184 B

    const int tid  = threadIdx.x;
    const int lane = tid & 31;
    const int wid  = tid >> 5;

    // finalizer scratch aliases tile 0 (only the single grid-last warp uses
    // it, after every co-resident warp has ticketed past its tile reads).
    unsigned* hist = (unsigned*)&s_tile[0][0];     // 256 * 4B

    // ---- slice coordinates: one 32-prior slice per warp ----
    const int s  = blockIdx.x * NWARP + wid;       // 0 .. SL_TOTAL-1
    const int b  = s / SL_PER_B;
    const int j  = s % SL_PER_B;
    const int p0 = j * WROWS;
    const int nr = min(WROWS, PRIORS - p0);        // 32 or 28
    const long long gw = (long long)b * PRIORS + p0;   // gw*81 % 4 == 0

    // ---- per-warp label-dtype detection: 32 int2 (256 B, L2-hot).
    // int64 labels in [0,81) -> odd words all zero; 32 random int32 labels
    // all-zero has p = (1/81)^32 ~ 1e-61.
    const int  bad  = ((const int2*)ct)[lane].y;
    const bool is64 = !__any_sync(FULLMASK, bad);

    // ---- stage this warp's slice: coalesced float4 loads, packed STS.64 ----
    {
        const float4* src4 = (const float4*)(conf + gw * CLASSES);
        uint2* dst8 = (uint2*)&s_tile[wid][0];
        const int n4 = (nr * CLASSES) >> 2;        // 648 or 567
        #pragma unroll 4
        for (int q = lane; q < n4; q += 32) {
            const float4 v = src4[q];
            __half2 a = __floats2half2_rn(v.x, v.y);
            __half2 c = __floats2half2_rn(v.z, v.w);
            uint2 u;
            u.x = *reinterpret_cast<const uint32_t*>(&a);
            u.y = *reinterpret_cast<const uint32_t*>(&c);
            dst8[q] = u;
        }
    }
    __syncwarp();

    float my_all = 0.f, my_pos = 0.f, my_loc = 0.f;
    int   my_cnt = 0;

    if (lane < nr) {
        // label + loc loads issued up front; latency hides under the exps
        const int t = is64 ? (int)((const long long*)ct)[gw + lane]
                           : ((const int*)ct)[gw + lane];
        const float4 d4 = loc[gw + lane];
        const float4 t4 = loct[gw + lane];

        // Row L starts at half 81*L. Read the aligned 82-half window starting
        // at half2 floor(81*L/2); subtract the one stray exp (even L:
        // trailing .y; odd L: leading .x). Windows stay inside nr*81 halves
        // for nr in {32, 28}.
        const __half2* h2p = (const __half2*)&s_tile[wid][0] + ((81 * lane) >> 1);
        float e0 = 0.f, e1 = 0.f, e2 = 0.f, e3 = 0.f;
        #pragma unroll
        for (int q = 0; q < 40; q += 4) {
            const float2 f0 = __half22float2(h2p[q]);
            const float2 f1 = __half22float2(h2p[q + 1]);
            const float2 f2 = __half22float2(h2p[q + 2]);
            const float2 f3 = __half22float2(h2p[q + 3]);
            e0 += __expf(f0.x) + __expf(f0.y);
            e1 += __expf(f1.x) + __expf(f1.y);
            e2 += __expf(f2.x) + __expf(f2.y);
            e3 += __expf(f3.x) + __expf(f3.y);
        }
        const float2 fl = __half22float2(h2p[40]);
        float sum = (((e0 + e1) + (e2 + e3)) + __expf(fl.x)) + __expf(fl.y);
        const float stray = (lane & 1) ? __half2float(__low2half(h2p[0]))
                                       : fl.y;
        sum -= __expf(stray);

        const float tv  = __half2float(s_tile[wid][81 * lane + t]);
        const float nll = __logf(sum) - tv;
        const bool  pos = (t > 0);

        g_vrank[gw + lane] = pos ? 0.f : nll;
        my_all = nll;
        if (pos) {
            my_pos = nll; my_cnt = 1;
            float dx = d4.x - t4.x, dy = d4.y - t4.y;
            float dz = d4.z - t4.z, dw = d4.w - t4.w;
            float ax = fabsf(dx), ay = fabsf(dy), az = fabsf(dz), aw = fabsf(dw);
            my_loc = ((ax < 1.f) ? 0.5f * dx * dx : ax - 0.5f)
                   + ((ay < 1.f) ? 0.5f * dy * dy : ay - 0.5f)
                   + ((az < 1.f) ? 0.5f * dz * dz : az - 0.5f)
                   + ((aw < 1.f) ? 0.5f * dw * dw : aw - 0.5f);
        }
    }

    // ---- warp reduce + lane-0 flush (no block interaction) ----
    #pragma unroll
    for (int o = 16; o > 0; o >>= 1) {
        my_all += __shfl_down_sync(FULLMASK, my_all, o);
        my_pos += __shfl_down_sync(FULLMASK, my_pos, o);
        my_loc += __shfl_down_sync(FULLMASK, my_loc, o);
        my_cnt += __shfl_down_sync(FULLMASK, my_cnt, o);
    }
    unsigned ticket = 0;
    if (lane == 0) {
        atomicAdd(&g_sum_all[b], (double)my_all);
        atomicAdd(&g_sum_pos[b], (double)my_pos);
        atomicAdd(&g_sum_loc[b], (double)my_loc);
        atomicAdd(&g_num_pos[b], my_cnt);
        __threadfence();
        ticket = atomicAdd(&g_done, 1u);
    }
    ticket = __shfl_sync(FULLMASK, ticket, 0);
    if (ticket != (unsigned)(SL_TOTAL - 1)) return;

    // ================== warp-only finalizer (grid-last warp) ================
    __threadfence();
    const int    npb  = ((volatile int*)g_num_pos)[lane];
    const double sall = ((volatile double*)g_sum_all)[lane];
    const double sloc = ((volatile double*)g_sum_loc)[lane];
    const long long nn = min((long long)3 * npb, (long long)(PRIORS - 1));
    const bool rare = (nn < (long long)(PRIORS - npb));
    const unsigned rmask0 = __ballot_sync(FULLMASK, rare);
    {
        double c = rare ? 0.0 : sall;
        double l = sloc;
        int    n = npb;
        #pragma unroll
        for (int o = 16; o > 0; o >>= 1) {
            c += __shfl_down_sync(FULLMASK, c, o);
            l += __shfl_down_sync(FULLMASK, l, o);
            n += __shfl_down_sync(FULLMASK, n, o);
        }
        // lane 0 carries the running totals
        double loss_c = c;
        unsigned rm = rmask0;
        // rare path: exact top-k radix select per flagged batch (expected none)
        while (rm) {
            const int rb = __ffs(rm) - 1;
            rm &= rm - 1;
            const int npr = ((volatile int*)g_num_pos)[rb];
            int kk = (int)min((long long)3 * npr, (long long)(PRIORS - 1));
            kk = __shfl_sync(FULLMASK, kk, 0);     // uniform
            const float* v = g_vrank + (long long)rb * PRIORS;
            unsigned prefix = 0;
            for (int shift = 24; shift >= 0; shift -= 8) {
                for (int i = lane; i < 256; i += 32) hist[i] = 0;
                __syncwarp();
                const unsigned mask_hi =
                    (shift == 24) ? 0u : (0xFFFFFFFFu << (shift + 8));
                for (int i = lane; i < PRIORS; i += 32) {
                    const unsigned bits = __float_as_uint(v[i]);
                    if ((bits & mask_hi) == prefix)
                        atomicAdd(&hist[(bits >> shift) & 255], 1u);
                }
                __syncwarp();
                int nk = 0; unsigned npref = 0;
                if (lane == 0) {
                    int acc = 0, bin = 255;
                    for (; bin > 0; --bin) {
                        if (acc + (int)hist[bin] >= kk) break;
                        acc += (int)hist[bin];
                    }
                    npref = prefix | ((unsigned)bin << shift);
                    nk    = kk - acc;
                }
                __syncwarp();
                prefix = __shfl_sync(FULLMASK, npref, 0);
                kk     = __shfl_sync(FULLMASK, nk, 0);
            }
            double local = 0.0;
            for (int i = lane; i < PRIORS; i += 32) {
                const unsigned bits = __float_as_uint(v[i]);
                if (bits > prefix) local += (double)v[i];
            }
            #pragma unroll
            for (int o = 16; o > 0; o >>= 1)
                local += __shfl_down_sync(FULLMASK, local, o);
            if (lane == 0) {
                loss_c += ((volatile double*)g_sum_pos)[rb] + local +
                          (double)kk * (double)__uint_as_float(prefix);
            }
        }

        if (lane == 0) {
            const double N = (double)n;
            if (out_size >= 1) out[0] = (float)(loss_c / N);
            if (out_size >= 2) out[1] = (float)(l / N);
        }
    }

    // reset globals for the next graph replay (lane covers all 32 batches)
    g_sum_all[lane] = 0.0; g_sum_pos[lane] = 0.0;
    g_sum_loc[lane] = 0.0; g_num_pos[lane] = 0;
    if (lane == 0) g_done = 0;
}

extern "C" void kernel_launch(void* const* d_in, const int* in_sizes, int n_in,
                              void* d_out, int out_size) {
    const float*  conf = (const float*)d_in[0];
    const float4* loc  = (const float4*)d_in[1];
    const void*   ct   = d_in[2];
    const float4* loct = (const float4*)d_in[3];
    float*        out  = (float*)d_out;
    (void)in_sizes; (void)n_in;

    k_main<<<GRID_MAIN, TPB>>>(conf, loc, ct, loct, out, out_size);
}

// round 16
// speedup vs baseline: 1.2587x; 1.2587x over previous
#include <cuda_runtime.h>
#include <cuda_fp16.h>
#include <cstdint>
#include <math.h>
#include <float.h>

// ---------------------------------------------------------------------------
// MultiBoxLoss (SSD) fused loss.  B=32, P=8732, C=81.
//   out[0] = loss_c / N, out[1] = loss_l / N
// Warp-private tiles (R12 structure, 4 warps/block): each warp stages its own
// 32-prior conf slice to its own fp16 smem region (coalesced float4 loads,
// packed STS.64) and syncs with __syncwarp() only -- no block barrier in the
// hot path; block-end reduce amortizes the flush over 4 warps.
// nll = lse - tgt_logit is both the CE term and the hard-negative rank key.
// Common case (num_neg >= #negatives): loss_c = sum of ALL nll.
// Rare case: exact top-k via radix select (tie-order invariant for a sum).
// ---------------------------------------------------------------------------

#define BATCH    32
#define PRIORS   8732
#define CLASSES  81
#define TPB      128                               // 4 autonomous warps
#define NW       (TPB / 32)
#define WROWS    32                                // priors per warp slice
#define WHALF    (WROWS * CLASSES)                 // 2592 halves (5184 B)
#define SL_PER_B ((PRIORS + WROWS - 1) / WROWS)    // 273
#define SL_TOTAL (SL_PER_B * BATCH)                // 8736
#define GRID_MAIN (SL_TOTAL / NW)                  // 2184
#define FULLMASK 0xFFFFFFFFu

// Device-global scratch; statically zero-init. The fused finalizer resets
// everything at the end of each call -> graph replays are deterministic.
__device__ double   g_sum_all[BATCH];
__device__ double   g_sum_pos[BATCH];
__device__ double   g_sum_loc[BATCH];
__device__ int      g_num_pos[BATCH];
__device__ unsigned g_done   = 0;
__device__ float    g_vrank[BATCH * PRIORS];

__global__ void __launch_bounds__(TPB, 11)
k_main(const float* __restrict__ conf,
       const float4* __restrict__ loc,
       const void*  __restrict__ ct,
       const float4* __restrict__ loct,
       float* __restrict__ out, int out_size) {
    __shared__ __align__(16) __half s_tile[NW][WHALF];   // 4 x 5184 B
    __shared__ float    s_f[NW * 3];
    __shared__ int      s_i[NW];
    __shared__ unsigned s_last;
    __shared__ unsigned sh_prefix, sh_rare;
    __shared__ int      sh_k;
    __shared__ double   sh_lc, sh_ll;
    __shared__ long long sh_n;

    // Rare-path scratch aliases the tile (only the single last block uses it,
    // after all tile reads, with __syncthreads() separating uses).
    double*   dred = (double*)&s_tile[0][0];       // 128 * 8B
    unsigned* hist = (unsigned*)&s_tile[0][0] + 256;

    const int tid  = threadIdx.x;
    const int lane = tid & 31;
    const int wid  = tid >> 5;

    // ---- slice coordinates: one 32-prior slice per warp ----
    const int s  = blockIdx.x * NW + wid;          // 0 .. SL_TOTAL-1
    const int b  = s / SL_PER_B;
    const int j  = s % SL_PER_B;
    const int p0 = j * WROWS;
    const int nr = min(WROWS, PRIORS - p0);        // 32 or 28
    const long long gw = (long long)b * PRIORS + p0;   // gw*81 % 4 == 0

    // ---- per-warp label-dtype detection: 32 int2 (256 B, L2-hot).
    // int64 labels in [0,81) -> odd words all zero; 32 random int32 labels
    // all-zero has p = (1/81)^32 ~ 1e-61.
    const int  bad  = ((const int2*)ct)[lane].y;
    const bool is64 = !__any_sync(FULLMASK, bad);

    // ---- stage this warp's slice: coalesced float4 loads, packed STS.64 ----
    {
        const float4* src4 = (const float4*)(conf + gw * CLASSES);
        uint2* dst8 = (uint2*)&s_tile[wid][0];
        const int n4 = (nr * CLASSES) >> 2;        // 648 or 567
        #pragma unroll 4
        for (int q = lane; q < n4; q += 32) {
            const float4 v = src4[q];
            __half2 a = __floats2half2_rn(v.x, v.y);
            __half2 c = __floats2half2_rn(v.z, v.w);
            uint2 u;
            u.x = *reinterpret_cast<const uint32_t*>(&a);
            u.y = *reinterpret_cast<const uint32_t*>(&c);
            dst8[q] = u;
        }
    }
    __syncwarp();          // warp-scope: staging visible to this warp only

    float my_all = 0.f, my_pos = 0.f, my_loc = 0.f;
    int   my_cnt = 0;

    if (lane < nr) {
        // label + loc loads issued up front; latency hides under the exps
        const int t = is64 ? (int)((const long long*)ct)[gw + lane]
                           : ((const int*)ct)[gw + lane];
        const float4 d4 = loc[gw + lane];
        const float4 t4 = loct[gw + lane];

        // Row L starts at half 81*L. Read the aligned 82-half window starting
        // at half2 floor(81*L/2); subtract the one stray exp (even L:
        // trailing .y; odd L: leading .x). Windows stay inside nr*81 halves
        // for nr in {32, 28}.
        const __half2* h2p = (const __half2*)&s_tile[wid][0] + ((81 * lane) >> 1);
        float e0 = 0.f, e1 = 0.f, e2 = 0.f, e3 = 0.f;
        #pragma unroll
        for (int q = 0; q < 40; q += 4) {
            const float2 f0 = __half22float2(h2p[q]);
            const float2 f1 = __half22float2(h2p[q + 1]);
            const float2 f2 = __half22float2(h2p[q + 2]);
            const float2 f3 = __half22float2(h2p[q + 3]);
            e0 += __expf(f0.x) + __expf(f0.y);
            e1 += __expf(f1.x) + __expf(f1.y);
            e2 += __expf(f2.x) + __expf(f2.y);
            e3 += __expf(f3.x) + __expf(f3.y);
        }
        const float2 fl = __half22float2(h2p[40]);
        float sum = (((e0 + e1) + (e2 + e3)) + __expf(fl.x)) + __expf(fl.y);
        const float stray = (lane & 1) ? __half2float(__low2half(h2p[0]))
                                       : fl.y;
        sum -= __expf(stray);

        const float tv  = __half2float(s_tile[wid][81 * lane + t]);
        const float nll = __logf(sum) - tv;
        const bool  pos = (t > 0);

        g_vrank[gw + lane] = pos ? 0.f : nll;
        my_all = nll;
        if (pos) {
            my_pos = nll; my_cnt = 1;
            float dx = d4.x - t4.x, dy = d4.y - t4.y;
            float dz = d4.z - t4.z, dw = d4.w - t4.w;
            float ax = fabsf(dx), ay = fabsf(dy), az = fabsf(dz), aw = fabsf(dw);
            my_loc = ((ax < 1.f) ? 0.5f * dx * dx : ax - 0.5f)
                   + ((ay < 1.f) ? 0.5f * dy * dy : ay - 0.5f)
                   + ((az < 1.f) ? 0.5f * dz * dz : az - 0.5f)
                   + ((aw < 1.f) ? 0.5f * dw * dw : aw - 0.5f);
        }
    }

    // ---- block reduce (warp shfl, then NW leaders; first block barrier) ----
    #pragma unroll
    for (int o = 16; o > 0; o >>= 1) {
        my_all += __shfl_down_sync(FULLMASK, my_all, o);
        my_pos += __shfl_down_sync(FULLMASK, my_pos, o);
        my_loc += __shfl_down_sync(FULLMASK, my_loc, o);
        my_cnt += __shfl_down_sync(FULLMASK, my_cnt, o);
    }
    if (lane == 0) {
        s_f[wid] = my_all; s_f[NW + wid] = my_pos; s_f[2 * NW + wid] = my_loc;
        s_i[wid] = my_cnt;
    }
    __syncthreads();
    // NOTE: warps of one block may span two batches (slices are contiguous);
    // flush per distinct batch present in the block. With NW=4 and 273 slices
    // per batch, a block covers at most 2 batches.
    if (tid == 0) {
        const int b_first = (blockIdx.x * NW) / SL_PER_B;
        const int b_last  = (blockIdx.x * NW + NW - 1) / SL_PER_B;
        if (b_first == b_last) {
            float an = 0.f, pn = 0.f, lc = 0.f; int nc = 0;
            #pragma unroll
            for (int w = 0; w < NW; w++) {
                an += s_f[w]; pn += s_f[NW + w]; lc += s_f[2 * NW + w]; nc += s_i[w];
            }
            atomicAdd(&g_sum_all[b_first], (double)an);
            atomicAdd(&g_sum_pos[b_first], (double)pn);
            atomicAdd(&g_sum_loc[b_first], (double)lc);
            atomicAdd(&g_num_pos[b_first], nc);
        } else {
            float an0 = 0.f, pn0 = 0.f, lc0 = 0.f; int nc0 = 0;
            float an1 = 0.f, pn1 = 0.f, lc1 = 0.f; int nc1 = 0;
            #pragma unroll
            for (int w = 0; w < NW; w++) {
                const int wb = (blockIdx.x * NW + w) / SL_PER_B;
                if (wb == b_first) {
                    an0 += s_f[w]; pn0 += s_f[NW + w]; lc0 += s_f[2 * NW + w]; nc0 += s_i[w];
                } else {
                    an1 += s_f[w]; pn1 += s_f[NW + w]; lc1 += s_f[2 * NW + w]; nc1 += s_i[w];
                }
            }
            atomicAdd(&g_sum_all[b_first], (double)an0);
            atomicAdd(&g_sum_pos[b_first], (double)pn0);
            atomicAdd(&g_sum_loc[b_first], (double)lc0);
            atomicAdd(&g_num_pos[b_first], nc0);
            atomicAdd(&g_sum_all[b_last], (double)an1);
            atomicAdd(&g_sum_pos[b_last], (double)pn1);
            atomicAdd(&g_sum_loc[b_last], (double)lc1);
            atomicAdd(&g_num_pos[b_last], nc1);
        }
        __threadfence();
        s_last = atomicAdd(&g_done, 1u);
    }
    __syncthreads();
    if (s_last != (unsigned)(gridDim.x - 1)) return;

    // ======================= fused finalizer (last block) ===================
    __threadfence();
    if (tid < 32) {
        const int    npb  = ((volatile int*)g_num_pos)[tid];
        const double sall = ((volatile double*)g_sum_all)[tid];
        const double sloc = ((volatile double*)g_sum_loc)[tid];
        const long long nn = min((long long)3 * npb, (long long)(PRIORS - 1));
        const bool rare = (nn < (long long)(PRIORS - npb));
        const unsigned rm = __ballot_sync(FULLMASK, rare);
        double c = rare ? 0.0 : sall;
        double l = sloc;
        int    n = npb;
        #pragma unroll
        for (int o = 16; o > 0; o >>= 1) {
            c += __shfl_down_sync(FULLMASK, c, o);
            l += __shfl_down_sync(FULLMASK, l, o);
            n += __shfl_down_sync(FULLMASK, n, o);
        }
        if (tid == 0) { sh_lc = c; sh_ll = l; sh_n = n; sh_rare = rm; }
    }
    __syncthreads();

    double loss_c = sh_lc;
    unsigned rmask = sh_rare;
    // rare path: exact top-k radix select per flagged batch (expected none)
    while (rmask) {
        const int rb = __ffs(rmask) - 1;
        rmask &= rmask - 1;
        const int npb = ((volatile int*)g_num_pos)[rb];
        int kk = (int)min((long long)3 * npb, (long long)(PRIORS - 1));
        const float* v = g_vrank + (long long)rb * PRIORS;
        unsigned prefix = 0;
        for (int shift = 24; shift >= 0; shift -= 8) {
            for (int i = tid; i < 256; i += TPB) hist[i] = 0;
            __syncthreads();
            const unsigned mask_hi =
                (shift == 24) ? 0u : (0xFFFFFFFFu << (shift + 8));
            for (int i = tid; i < PRIORS; i += TPB) {
                const unsigned bits = __float_as_uint(v[i]);
                if ((bits & mask_hi) == prefix)
                    atomicAdd(&hist[(bits >> shift) & 255], 1u);
            }
            __syncthreads();
            if (tid == 0) {
                int acc = 0, bin = 255;
                for (; bin > 0; --bin) {
                    if (acc + (int)hist[bin] >= kk) break;
                    acc += (int)hist[bin];
                }
                sh_prefix = prefix | ((unsigned)bin << shift);
                sh_k      = kk - acc;
            }
            __syncthreads();
            prefix = sh_prefix; kk = sh_k;
            __syncthreads();
        }
        double local = 0.0;
        for (int i = tid; i < PRIORS; i += TPB) {
            const unsigned bits = __float_as_uint(v[i]);
            if (bits > prefix) local += (double)v[i];
        }
        dred[tid] = local;
        __syncthreads();
        for (int st = 64; st > 0; st >>= 1) {
            if (tid < st) dred[tid] += dred[tid + st];
            __syncthreads();
        }
        if (tid == 0) {
            loss_c += ((volatile double*)g_sum_pos)[rb] + dred[0] +
                      (double)kk * (double)__uint_as_float(prefix);
        }
        __syncthreads();
    }

    if (tid == 0) {
        const double N = (double)sh_n;
        if (out_size >= 1) out[0] = (float)(loss_c / N);
        if (out_size >= 2) out[1] = (float)(sh_ll / N);
    }

    // reset globals for the next graph replay
    if (tid < BATCH) {
        g_sum_all[tid] = 0.0; g_sum_pos[tid] = 0.0;
        g_sum_loc[tid] = 0.0; g_num_pos[tid] = 0;
    }
    if (tid == 0) g_done = 0;
}

extern "C" void kernel_launch(void* const* d_in, const int* in_sizes, int n_in,
                              void* d_out, int out_size) {
    const float*  conf = (const float*)d_in[0];
    const float4* loc  = (const float4*)d_in[1];
    const void*   ct   = d_in[2];
    const float4* loct = (const float4*)d_in[3];
    float*        out  = (float*)d_out;
    (void)in_sizes; (void)n_in;

    k_main<<<GRID_MAIN, TPB>>>(conf, loc, ct, loct, out, out_size);
}